// round 13
// baseline (speedup 1.0000x reference)
#include <cuda_runtime.h>
#include <cuda_bf16.h>
#include <cstdint>

#define T_STEPS 512
#define B_SZ 32
#define D_SZ 1024
#define H_SZ 1024
#define G3 3072
#define KEXT 3072
#define NBLK 128
#define RTHREADS 256
#define NCHUNK (KEXT / 64)

typedef unsigned long long u64;

// -------------------- device scratch --------------------
// gi in TRANSPOSED layout: [t][n(3072)][b(32)]
__device__ float g_gi[(size_t)T_STEPS * G3 * B_SZ];
__device__ __nv_bfloat16 g_aext[(size_t)T_STEPS * B_SZ * KEXT]; // [m][kext]
__device__ __nv_bfloat16 g_bext[(size_t)G3 * KEXT];             // [n][kext]
__device__ __nv_bfloat16 g_wt2[(size_t)NBLK * 65536];  // per-block smem image (Wh|Wl)
// h slab: [buf][hh: [w8][k16 8][m32][kk16] | hl at +32768 elems]
__device__ __nv_bfloat16 g_hslab[2][65536];
__device__ unsigned g_bar;

// -------------------- smem / mma helpers (base-target ISA only) -------------
__device__ __forceinline__ uint32_t smem_u32(const void* p) {
    uint32_t a;
    asm("{ .reg .u64 t; cvta.to.shared.u64 t, %1; cvt.u32.u64 %0, t; }"
        : "=r"(a) : "l"(p));
    return a;
}
#define SW128(off) ((off) ^ (((off) >> 3) & 0x70))

__device__ __forceinline__ void cp16(uint32_t sm, const void* g) {
    asm volatile("cp.async.cg.shared.global [%0], [%1], 16;" :: "r"(sm), "l"(g));
}
#define CP_COMMIT() asm volatile("cp.async.commit_group;" ::: "memory")
#define CP_WAIT(n)  asm volatile("cp.async.wait_group %0;" :: "n"(n) : "memory")

__device__ __forceinline__ void ldm_x4(uint32_t* r, uint32_t addr) {
    asm volatile("ldmatrix.sync.aligned.m8n8.x4.shared.b16 {%0,%1,%2,%3}, [%4];"
                 : "=r"(r[0]), "=r"(r[1]), "=r"(r[2]), "=r"(r[3]) : "r"(addr));
}
__device__ __forceinline__ void mma16816(float* c, const uint32_t* a,
                                         uint32_t b0, uint32_t b1) {
    asm volatile(
        "mma.sync.aligned.m16n8k16.row.col.f32.bf16.bf16.f32 "
        "{%0,%1,%2,%3}, {%4,%5,%6,%7}, {%8,%9}, {%0,%1,%2,%3};"
        : "+f"(c[0]), "+f"(c[1]), "+f"(c[2]), "+f"(c[3])
        : "r"(a[0]), "r"(a[1]), "r"(a[2]), "r"(a[3]), "r"(b0), "r"(b1));
}

// -------------------- pack: W_hh -> per-block swizzled bf16 split -----------
__global__ void pack_kernel(const float* __restrict__ W_hh) {
    int o = blockIdx.x * blockDim.x + threadIdx.x;   // [k 1024][inner 4096]
    int k = o >> 12;
    int inner = o & 4095;
    float w = 0.0f;
    int r, bx;
    if (inner < 3072) {
        int g = inner >> 10, rem = inner & 1023;
        bx = rem >> 3;
        r = g * 8 + (rem & 7);
        w = W_hh[(size_t)k * G3 + inner];
    } else {
        int pi = inner - 3072;
        bx = pi & 127;
        r = 24 + (pi >> 7);
    }
    __nv_bfloat16 hi = __float2bfloat16(w);
    __nv_bfloat16 lo = __float2bfloat16(w - __bfloat162float(hi));
    int idx = (k >> 4) * 512 + r * 16 +
              (((((k >> 3) & 1) ^ ((r >> 2) & 1))) << 3) + (k & 7);
    size_t base = (size_t)bx * 65536;
    g_wt2[base + idx] = hi;
    g_wt2[base + 32768 + idx] = lo;
    if (o < 2 * 65536)
        ((__nv_bfloat16*)g_hslab)[o] = __float2bfloat16(0.0f);
    if (o == 0) g_bar = 0u;   // per-launch reset: rnn barrier targets are absolute
}

// -------------------- convert A: X -> [xh | xl | xh] bf16 -------------------
__global__ void convA_kernel(const float* __restrict__ X) {
    int idx = blockIdx.x * blockDim.x + threadIdx.x;
    float4 v = *(const float4*)(X + (size_t)idx * 4);
    int m  = idx >> 8;
    int k4 = (idx & 255) * 4;
    __nv_bfloat16 h0 = __float2bfloat16(v.x), h1 = __float2bfloat16(v.y);
    __nv_bfloat16 h2 = __float2bfloat16(v.z), h3 = __float2bfloat16(v.w);
    __nv_bfloat16 l0 = __float2bfloat16(v.x - __bfloat162float(h0));
    __nv_bfloat16 l1 = __float2bfloat16(v.y - __bfloat162float(h1));
    __nv_bfloat16 l2 = __float2bfloat16(v.z - __bfloat162float(h2));
    __nv_bfloat16 l3 = __float2bfloat16(v.w - __bfloat162float(h3));
    __nv_bfloat162 hA = {h0, h1}, hB = {h2, h3}, lA = {l0, l1}, lB = {l2, l3};
    uint2 hp = {*(unsigned*)&hA, *(unsigned*)&hB};
    uint2 lp = {*(unsigned*)&lA, *(unsigned*)&lB};
    __nv_bfloat16* base = g_aext + (size_t)m * KEXT + k4;
    *(uint2*)base = hp;
    *(uint2*)(base + D_SZ) = lp;
    *(uint2*)(base + 2 * D_SZ) = hp;
}

// -------------------- convert B: W_ih^T -> [wh ; wh ; wl] [n][k] bf16 -------
__global__ void convB_kernel(const float* __restrict__ W) {
    __shared__ float tile[32][33];
    int n0 = blockIdx.x * 32, k0 = blockIdx.y * 32;
    int tx = threadIdx.x, ty = threadIdx.y;
#pragma unroll
    for (int j = 0; j < 4; j++) {
        int r = ty * 4 + j;
        tile[r][tx] = W[(size_t)(k0 + r) * G3 + n0 + tx];
    }
    __syncthreads();
#pragma unroll
    for (int j = 0; j < 4; j++) {
        int nl = ty * 4 + j;
        float w = tile[tx][nl];
        __nv_bfloat16 hi = __float2bfloat16(w);
        __nv_bfloat16 lo = __float2bfloat16(w - __bfloat162float(hi));
        __nv_bfloat16* row = g_bext + (size_t)(n0 + nl) * KEXT + k0 + tx;
        row[0] = hi;
        row[D_SZ] = hi;
        row[2 * D_SZ] = lo;
    }
}

// -------------------- mma.sync GEMM: gi = A_ext @ B_ext^T + bias ------------
// Epilogue transposes through SMEM and writes gi in [t][n][b] layout
// (contiguous 16KB regions per local t -> fully coalesced STG.128).
#define SM_BUF 32768
#define SM_TOTAL_G 67584            // max(2*SM_BUF, 128*132*4)

__device__ __forceinline__ void gg_load(const __nv_bfloat16* Ab,
                                        const __nv_bfloat16* Bb,
                                        int c, uint32_t sb, int buf, int tid) {
    size_t koff = (size_t)c * 64;
    uint32_t base = sb + buf * SM_BUF;
#pragma unroll
    for (int i = 0; i < 4; i++) {
        int idx = tid + i * 256;
        int row = idx >> 3, f4 = idx & 7;
        uint32_t sw = SW128((uint32_t)(row * 128 + f4 * 16));
        cp16(base + sw, Ab + (size_t)row * KEXT + koff + f4 * 8);
        cp16(base + 16384 + sw, Bb + (size_t)row * KEXT + koff + f4 * 8);
    }
    CP_COMMIT();
}

extern __shared__ unsigned char sm_gg[];
__global__ void __launch_bounds__(256, 2)
mmagemm_kernel(const float* __restrict__ bias) {
    uint32_t sb = smem_u32(sm_gg);
    int tid = threadIdx.x, wid = tid >> 5, lane = tid & 31;
    int n0 = blockIdx.x * 128, m0 = blockIdx.y * 128;
    int warp_m = wid & 3, warp_n = wid >> 2;

    uint32_t Ca[2], Ma[2];
#pragma unroll
    for (int mi = 0; mi < 2; mi++) {
        int row = warp_m * 32 + mi * 16 + (lane & 15);
        Ca[mi] = (uint32_t)(row * 128 + (lane >> 4) * 16);
        Ma[mi] = (uint32_t)((row & 7) << 4);
    }
    uint32_t Cb[4], Mb[4];
#pragma unroll
    for (int np = 0; np < 4; np++) {
        int row = warp_n * 64 + np * 16 + (lane & 7) + ((lane >> 4) << 3);
        Cb[np] = (uint32_t)(row * 128 + ((lane >> 3) & 1) * 16);
        Mb[np] = (uint32_t)((row & 7) << 4);
    }

    float acc[2][8][4];
#pragma unroll
    for (int mi = 0; mi < 2; mi++)
#pragma unroll
        for (int ni = 0; ni < 8; ni++)
#pragma unroll
            for (int q = 0; q < 4; q++) acc[mi][ni][q] = 0.0f;

    const __nv_bfloat16* Ab = g_aext + (size_t)m0 * KEXT;
    const __nv_bfloat16* Bb = g_bext + (size_t)n0 * KEXT;

    gg_load(Ab, Bb, 0, sb, 0, tid);

    int buf = 0;
    for (int c = 0; c < NCHUNK; c++) {
        if (c + 1 < NCHUNK) {
            gg_load(Ab, Bb, c + 1, sb, buf ^ 1, tid);
            CP_WAIT(1);
        } else {
            CP_WAIT(0);
        }
        __syncthreads();

        uint32_t a_sm = sb + buf * SM_BUF;
        uint32_t b_sm = a_sm + 16384;
#pragma unroll
        for (int k16 = 0; k16 < 4; k16++) {
            uint32_t af[2][4], bf[4][4];
#pragma unroll
            for (int mi = 0; mi < 2; mi++)
                ldm_x4(af[mi], a_sm + ((Ca[mi] + k16 * 32) ^ Ma[mi]));
#pragma unroll
            for (int np = 0; np < 4; np++)
                ldm_x4(bf[np], b_sm + ((Cb[np] + k16 * 32) ^ Mb[np]));
#pragma unroll
            for (int mi = 0; mi < 2; mi++)
#pragma unroll
                for (int ni = 0; ni < 8; ni++)
                    mma16816(acc[mi][ni], af[mi],
                             bf[ni >> 1][(ni & 1) * 2],
                             bf[ni >> 1][(ni & 1) * 2 + 1]);
        }
        __syncthreads();
        buf ^= 1;
    }

    // ---- epilogue: bias add + SMEM transpose -> gi[t][n][b] ----
    float* ts = (float*)sm_gg;     // [n_local 128][m_local 132] fp32
    int r = lane >> 2, q = (lane & 3) * 2;
    float bv[8][2];
#pragma unroll
    for (int ni = 0; ni < 8; ni++) {
        bv[ni][0] = bias[n0 + warp_n * 64 + ni * 8 + q];
        bv[ni][1] = bias[n0 + warp_n * 64 + ni * 8 + q + 1];
    }
#pragma unroll
    for (int mi = 0; mi < 2; mi++) {
#pragma unroll
        for (int ni = 0; ni < 8; ni++) {
            int n_l = warp_n * 64 + ni * 8 + q;
            int m_l0 = warp_m * 32 + mi * 16 + r;
            ts[n_l * 132 + m_l0]       = acc[mi][ni][0] + bv[ni][0];
            ts[(n_l + 1) * 132 + m_l0] = acc[mi][ni][1] + bv[ni][1];
            ts[n_l * 132 + m_l0 + 8]       = acc[mi][ni][2] + bv[ni][0];
            ts[(n_l + 1) * 132 + m_l0 + 8] = acc[mi][ni][3] + bv[ni][1];
        }
    }
    __syncthreads();
    int t0 = m0 >> 5;
#pragma unroll
    for (int i = 0; i < 16; i++) {
        int idx4 = tid + i * 256;          // 0..4095 float4 slots
        int t_l = idx4 >> 10;              // 1024 float4 per t region
        int rem = idx4 & 1023;
        int n_l = rem >> 3;
        int b4 = (rem & 7) * 4;
        float4 v = *(const float4*)&ts[n_l * 132 + t_l * 32 + b4];
        *(float4*)&g_gi[((size_t)(t0 + t_l) * G3 + n0 + n_l) * B_SZ + b4] = v;
    }
}

// -------------------- grid barrier (release-red + per-warp acquire poll) ----
__device__ __forceinline__ void grid_barrier_fast(int tnext) {
    __syncthreads();                 // all h publish STGs done
    if (threadIdx.x == 0)
        asm volatile("red.release.gpu.global.add.u32 [%0], %1;"
                     :: "l"(&g_bar), "r"(1u) : "memory");
    if ((threadIdx.x & 31) == 0) {
        unsigned target = (unsigned)tnext * NBLK;
        unsigned v;
        do {
            asm volatile("ld.acquire.gpu.b32 %0, [%1];"
                         : "=r"(v) : "l"(&g_bar) : "memory");
        } while ((int)(v - target) < 0);
    }
    __syncwarp();                    // warps proceed independently
}

// -------------------- persistent recurrent kernel: tensor-core matvec -------
#define STAGE_OFF 131072                 // 8 warps x 8KB (4 bufs x 2KB)
#define SRED_OFF  196608                 // 8 x 24 x 33 fp32
#define SOUT_OFF  222208                 // 32 x 9 fp32
#define RSM_TOTAL 223488

extern __shared__ unsigned char rsm[];
__global__ void __launch_bounds__(RTHREADS, 1)
rnn_kernel(const float* __restrict__ paddings, const float* __restrict__ b_hh,
           float* __restrict__ out, int out_size) {
    float* sred = (float*)(rsm + SRED_OFF);   // [8 warps][24 n][33] fp32
    float* sout = (float*)(rsm + SOUT_OFF);   // [32][9]
    uint32_t sWb = smem_u32(rsm);             // Wh at +0, Wl at +65536 (bytes)

    int tid = threadIdx.x, wid = tid >> 5, lane = tid & 31;
    int bx = blockIdx.x;
    int ci = wid, b = lane;
    int c = bx * 8 + ci;

    // load pre-swizzled weights (128KB) once
    {
        const float4* src = (const float4*)(g_wt2 + (size_t)bx * 65536);
        float4* dst = (float4*)rsm;
#pragma unroll
        for (int i = 0; i < 32; i++) dst[i * RTHREADS + tid] = src[i * RTHREADS + tid];
    }
    float bh_r = b_hh[c], bh_z = b_hh[H_SZ + c], bh_n = b_hh[2 * H_SZ + c];
    float hreg = 0.0f;
    __syncthreads();

    int ll = lane & 15;
    int half = ll >> 3;
    uint32_t wl_add = (lane >= 16) ? 65536u : 0u;
    uint32_t stg = smem_u32(rsm) + STAGE_OFF + wid * 8192;
    uint32_t a_lane_off = (uint32_t)((lane & 15) * 32 + (lane >> 4) * 16);
    uint32_t lo16 = (uint32_t)(lane * 16);

    const bool has_tail =
        (size_t)out_size >= (size_t)T_STEPS * B_SZ * H_SZ + 2u * B_SZ * H_SZ;

    for (int t = 0; t < T_STEPS; t++) {
        const char* hhg = (const char*)g_hslab[t & 1] + wid * 8192;
        const char* hlg = hhg + 65536;
        // gi loads: [t][n][b] layout -> lane-contiguous (1 wavefront each)
        size_t gbase = ((size_t)t * G3 + c) * B_SZ + b;
        float ir  = __ldg(&g_gi[gbase]);
        float iz  = __ldg(&g_gi[gbase + (size_t)H_SZ * B_SZ]);
        float in_ = __ldg(&g_gi[gbase + (size_t)2 * H_SZ * B_SZ]);
        float p   = __ldg(&paddings[t * B_SZ + b]);

        float acc1[2][3][4], acc2[2][3][4];
#pragma unroll
        for (int mt = 0; mt < 2; mt++)
#pragma unroll
            for (int nt = 0; nt < 3; nt++)
#pragma unroll
                for (int q = 0; q < 4; q++) { acc1[mt][nt][q] = 0.f; acc2[mt][nt][q] = 0.f; }

        // prologue: stage chunks 0..3 (4 commit groups in flight)
#pragma unroll
        for (int j = 0; j < 4; j++) {
            uint32_t dst = stg + j * 2048;
            const char* s0 = hhg + j * 1024;
            const char* s1 = hlg + j * 1024;
            cp16(dst + lo16, s0 + lo16);
            cp16(dst + 512 + lo16, s0 + 512 + lo16);
            cp16(dst + 1024 + lo16, s1 + lo16);
            cp16(dst + 1536 + lo16, s1 + 512 + lo16);
            CP_COMMIT();
        }

#pragma unroll
        for (int k16 = 0; k16 < 8; k16++) {
            if (k16 == 5)      { CP_WAIT(2); }
            else if (k16 == 6) { CP_WAIT(1); }
            else if (k16 == 7) { CP_WAIT(0); }
            else               { CP_WAIT(3); }

            // A fragments from staged smem
            uint32_t abase = stg + (k16 & 3) * 2048;
            uint32_t ah[2][4], al[2][4];
#pragma unroll
            for (int mt = 0; mt < 2; mt++) {
                uint32_t ad = abase + mt * 512 + a_lane_off;
                ldm_x4(ah[mt], ad);
                ldm_x4(al[mt], ad + 1024);
            }
            // refill this buffer with chunk k16+4 (program order after LDSM)
            if (k16 < 4) {
                uint32_t dst = abase;
                const char* s0 = hhg + (k16 + 4) * 1024;
                const char* s1 = hlg + (k16 + 4) * 1024;
                cp16(dst + lo16, s0 + lo16);
                cp16(dst + 512 + lo16, s0 + 512 + lo16);
                cp16(dst + 1024 + lo16, s1 + lo16);
                cp16(dst + 1536 + lo16, s1 + 512 + lo16);
                CP_COMMIT();
            }

            // weights: fused x4 — lanes 0-15 Wh rows, lanes 16-31 Wl rows
            int k16g = wid * 8 + k16;
            uint32_t W4[3][4];
#pragma unroll
            for (int nt = 0; nt < 3; nt++) {
                int n = nt * 8 + (ll & 7);
                uint32_t off = (uint32_t)(k16g * 1024 + n * 32 +
                               ((half ^ ((n >> 2) & 1)) << 4)) + wl_add;
                ldm_x4(W4[nt], sWb + off);
            }
#pragma unroll
            for (int mt = 0; mt < 2; mt++)
#pragma unroll
                for (int nt = 0; nt < 3; nt++) {
                    mma16816(acc1[mt][nt], ah[mt], W4[nt][0], W4[nt][1]);
                    mma16816(acc2[mt][nt], ah[mt], W4[nt][2], W4[nt][3]);
                    mma16816(acc1[mt][nt], al[mt], W4[nt][0], W4[nt][1]);
                }
        }

        // store partials: sred[(wid*24 + n)*33 + m]
#pragma unroll
        for (int mt = 0; mt < 2; mt++)
#pragma unroll
            for (int nt = 0; nt < 3; nt++)
#pragma unroll
                for (int q = 0; q < 4; q++) {
                    int m = mt * 16 + (lane >> 2) + ((q >> 1) << 3);
                    int n = nt * 8 + (lane & 3) * 2 + (q & 1);
                    sred[(wid * 24 + n) * 33 + m] = acc1[mt][nt][q] + acc2[mt][nt][q];
                }
        __syncthreads();

        // reduce 8 warps + gate math: thread = (ci, b)
        float ga = bh_r, gz = bh_z, gn = bh_n;
#pragma unroll
        for (int w = 0; w < 8; w++) {
            const float* bw = sred + w * 24 * 33;
            ga += bw[(0 + ci) * 33 + b];
            gz += bw[(8 + ci) * 33 + b];
            gn += bw[(16 + ci) * 33 + b];
        }
        float rg = 1.0f / (1.0f + __expf(-(ir + ga)));
        float zg = 1.0f / (1.0f + __expf(-(iz + gz)));
        float nn = tanhf(in_ + rg * gn);
        float hn = (1.0f - zg) * nn + zg * hreg;
        hn = p * hreg + (1.0f - p) * hn;
        hreg = hn;
        sout[b * 9 + ci] = hn;
        __syncthreads();

        // writers: out + split-bf16 publish of h into slab layout
        {
            int b2 = tid >> 3, cl = tid & 7;
            float v = sout[b2 * 9 + cl];
            int cg = bx * 8 + cl;
            out[(size_t)t * B_SZ * H_SZ + b2 * H_SZ + cg] = v;
            __nv_bfloat16 hh = __float2bfloat16(v);
            __nv_bfloat16 hl = __float2bfloat16(v - __bfloat162float(hh));
            int w = cg >> 7, k16i = (cg >> 4) & 7, kk = cg & 15;
            int hidx = ((w * 8 + k16i) * 32 + b2) * 16 + kk;
            __nv_bfloat16* hnx = g_hslab[(t + 1) & 1];
            hnx[hidx] = hh;
            hnx[32768 + hidx] = hl;
            if (t == T_STEPS - 1 && has_tail) {
                size_t tail = (size_t)T_STEPS * B_SZ * H_SZ;
                out[tail + b2 * H_SZ + cg] = v;
                out[tail + (size_t)B_SZ * H_SZ + b2 * H_SZ + cg] = v;
            }
        }
        if (t != T_STEPS - 1) grid_barrier_fast(t + 1);
    }
}

// -------------------- launch --------------------
extern "C" void kernel_launch(void* const* d_in, const int* in_sizes, int n_in,
                              void* d_out, int out_size) {
    const float* X        = (const float*)d_in[0];
    const float* paddings = (const float*)d_in[1];
    const float* W_ih     = (const float*)d_in[2];
    const float* W_hh     = (const float*)d_in[3];
    const float* b_ih     = (const float*)d_in[4];
    const float* b_hh     = (const float*)d_in[5];
    float* out = (float*)d_out;
    (void)in_sizes; (void)n_in;

    pack_kernel<<<(D_SZ * 4096) / 256, 256>>>(W_hh);

    convA_kernel<<<(T_STEPS * B_SZ * D_SZ / 4) / 256, 256>>>(X);
    convB_kernel<<<dim3(G3 / 32, D_SZ / 32), dim3(32, 8)>>>(W_ih);

    cudaFuncSetAttribute(mmagemm_kernel,
                         cudaFuncAttributeMaxDynamicSharedMemorySize, SM_TOTAL_G);
    mmagemm_kernel<<<dim3(G3 / 128, (T_STEPS * B_SZ) / 128), 256, SM_TOTAL_G>>>(b_ih);

    cudaFuncSetAttribute(rnn_kernel,
                         cudaFuncAttributeMaxDynamicSharedMemorySize, RSM_TOTAL);
    rnn_kernel<<<NBLK, RTHREADS, RSM_TOTAL>>>(paddings, b_hh, out, out_size);
}

// round 14
// speedup vs baseline: 1.1711x; 1.1711x over previous
#include <cuda_runtime.h>
#include <cuda_bf16.h>
#include <cstdint>

#define T_STEPS 512
#define B_SZ 32
#define D_SZ 1024
#define H_SZ 1024
#define G3 3072
#define KEXT 3072
#define NBLK 128
#define RTHREADS 256
#define NCHUNK (KEXT / 64)

typedef unsigned long long u64;

// -------------------- device scratch --------------------
// gi in TRANSPOSED layout: [t][n(3072)][b(32)]
__device__ float g_gi[(size_t)T_STEPS * G3 * B_SZ];
__device__ __nv_bfloat16 g_aext[(size_t)T_STEPS * B_SZ * KEXT]; // [m][kext]
__device__ __nv_bfloat16 g_bext[(size_t)G3 * KEXT];             // [n][kext]
__device__ __nv_bfloat16 g_wt2[(size_t)NBLK * 65536];  // per-block smem image (Wh|Wl)
// h slab: [buf][hh: [w8][k16 8][m32][kk16] | hl at +32768 elems]
__device__ __nv_bfloat16 g_hslab[2][65536];
__device__ unsigned g_bar;

// -------------------- smem / mma helpers (base-target ISA only) -------------
__device__ __forceinline__ uint32_t smem_u32(const void* p) {
    uint32_t a;
    asm("{ .reg .u64 t; cvta.to.shared.u64 t, %1; cvt.u32.u64 %0, t; }"
        : "=r"(a) : "l"(p));
    return a;
}
#define SW128(off) ((off) ^ (((off) >> 3) & 0x70))

__device__ __forceinline__ void cp16(uint32_t sm, const void* g) {
    asm volatile("cp.async.cg.shared.global [%0], [%1], 16;" :: "r"(sm), "l"(g));
}
#define CP_COMMIT() asm volatile("cp.async.commit_group;" ::: "memory")
#define CP_WAIT(n)  asm volatile("cp.async.wait_group %0;" :: "n"(n) : "memory")

__device__ __forceinline__ void ldm_x4(uint32_t* r, uint32_t addr) {
    asm volatile("ldmatrix.sync.aligned.m8n8.x4.shared.b16 {%0,%1,%2,%3}, [%4];"
                 : "=r"(r[0]), "=r"(r[1]), "=r"(r[2]), "=r"(r[3]) : "r"(addr));
}
__device__ __forceinline__ void mma16816(float* c, const uint32_t* a,
                                         uint32_t b0, uint32_t b1) {
    asm volatile(
        "mma.sync.aligned.m16n8k16.row.col.f32.bf16.bf16.f32 "
        "{%0,%1,%2,%3}, {%4,%5,%6,%7}, {%8,%9}, {%0,%1,%2,%3};"
        : "+f"(c[0]), "+f"(c[1]), "+f"(c[2]), "+f"(c[3])
        : "r"(a[0]), "r"(a[1]), "r"(a[2]), "r"(a[3]), "r"(b0), "r"(b1));
}

// -------------------- pack: W_hh -> per-block swizzled bf16 split -----------
__global__ void pack_kernel(const float* __restrict__ W_hh) {
    int o = blockIdx.x * blockDim.x + threadIdx.x;   // [k 1024][inner 4096]
    int k = o >> 12;
    int inner = o & 4095;
    float w = 0.0f;
    int r, bx;
    if (inner < 3072) {
        int g = inner >> 10, rem = inner & 1023;
        bx = rem >> 3;
        r = g * 8 + (rem & 7);
        w = W_hh[(size_t)k * G3 + inner];
    } else {
        int pi = inner - 3072;
        bx = pi & 127;
        r = 24 + (pi >> 7);
    }
    __nv_bfloat16 hi = __float2bfloat16(w);
    __nv_bfloat16 lo = __float2bfloat16(w - __bfloat162float(hi));
    int idx = (k >> 4) * 512 + r * 16 +
              (((((k >> 3) & 1) ^ ((r >> 2) & 1))) << 3) + (k & 7);
    size_t base = (size_t)bx * 65536;
    g_wt2[base + idx] = hi;
    g_wt2[base + 32768 + idx] = lo;
    if (o < 2 * 65536)
        ((__nv_bfloat16*)g_hslab)[o] = __float2bfloat16(0.0f);
}

// -------------------- convert A: X -> [xh | xl | xh] bf16 -------------------
__global__ void convA_kernel(const float* __restrict__ X) {
    int idx = blockIdx.x * blockDim.x + threadIdx.x;
    float4 v = *(const float4*)(X + (size_t)idx * 4);
    int m  = idx >> 8;
    int k4 = (idx & 255) * 4;
    __nv_bfloat16 h0 = __float2bfloat16(v.x), h1 = __float2bfloat16(v.y);
    __nv_bfloat16 h2 = __float2bfloat16(v.z), h3 = __float2bfloat16(v.w);
    __nv_bfloat16 l0 = __float2bfloat16(v.x - __bfloat162float(h0));
    __nv_bfloat16 l1 = __float2bfloat16(v.y - __bfloat162float(h1));
    __nv_bfloat16 l2 = __float2bfloat16(v.z - __bfloat162float(h2));
    __nv_bfloat16 l3 = __float2bfloat16(v.w - __bfloat162float(h3));
    __nv_bfloat162 hA = {h0, h1}, hB = {h2, h3}, lA = {l0, l1}, lB = {l2, l3};
    uint2 hp = {*(unsigned*)&hA, *(unsigned*)&hB};
    uint2 lp = {*(unsigned*)&lA, *(unsigned*)&lB};
    __nv_bfloat16* base = g_aext + (size_t)m * KEXT + k4;
    *(uint2*)base = hp;
    *(uint2*)(base + D_SZ) = lp;
    *(uint2*)(base + 2 * D_SZ) = hp;
}

// -------------------- convert B: W_ih^T -> [wh ; wh ; wl] [n][k] bf16 -------
__global__ void convB_kernel(const float* __restrict__ W) {
    __shared__ float tile[32][33];
    int n0 = blockIdx.x * 32, k0 = blockIdx.y * 32;
    int tx = threadIdx.x, ty = threadIdx.y;
#pragma unroll
    for (int j = 0; j < 4; j++) {
        int r = ty * 4 + j;
        tile[r][tx] = W[(size_t)(k0 + r) * G3 + n0 + tx];
    }
    __syncthreads();
#pragma unroll
    for (int j = 0; j < 4; j++) {
        int nl = ty * 4 + j;
        float w = tile[tx][nl];
        __nv_bfloat16 hi = __float2bfloat16(w);
        __nv_bfloat16 lo = __float2bfloat16(w - __bfloat162float(hi));
        __nv_bfloat16* row = g_bext + (size_t)(n0 + nl) * KEXT + k0 + tx;
        row[0] = hi;
        row[D_SZ] = hi;
        row[2 * D_SZ] = lo;
    }
}

// -------------------- mma.sync GEMM: gi = A_ext @ B_ext^T + bias ------------
// Epilogue transposes through SMEM and writes gi in [t][n][b] layout
// (contiguous 16KB regions per local t -> fully coalesced STG.128).
#define SM_BUF 32768
#define SM_TOTAL_G 67584            // max(2*SM_BUF, 128*132*4)

__device__ __forceinline__ void gg_load(const __nv_bfloat16* Ab,
                                        const __nv_bfloat16* Bb,
                                        int c, uint32_t sb, int buf, int tid) {
    size_t koff = (size_t)c * 64;
    uint32_t base = sb + buf * SM_BUF;
#pragma unroll
    for (int i = 0; i < 4; i++) {
        int idx = tid + i * 256;
        int row = idx >> 3, f4 = idx & 7;
        uint32_t sw = SW128((uint32_t)(row * 128 + f4 * 16));
        cp16(base + sw, Ab + (size_t)row * KEXT + koff + f4 * 8);
        cp16(base + 16384 + sw, Bb + (size_t)row * KEXT + koff + f4 * 8);
    }
    CP_COMMIT();
}

extern __shared__ unsigned char sm_gg[];
__global__ void __launch_bounds__(256, 2)
mmagemm_kernel(const float* __restrict__ bias) {
    uint32_t sb = smem_u32(sm_gg);
    int tid = threadIdx.x, wid = tid >> 5, lane = tid & 31;
    int n0 = blockIdx.x * 128, m0 = blockIdx.y * 128;
    int warp_m = wid & 3, warp_n = wid >> 2;

    uint32_t Ca[2], Ma[2];
#pragma unroll
    for (int mi = 0; mi < 2; mi++) {
        int row = warp_m * 32 + mi * 16 + (lane & 15);
        Ca[mi] = (uint32_t)(row * 128 + (lane >> 4) * 16);
        Ma[mi] = (uint32_t)((row & 7) << 4);
    }
    uint32_t Cb[4], Mb[4];
#pragma unroll
    for (int np = 0; np < 4; np++) {
        int row = warp_n * 64 + np * 16 + (lane & 7) + ((lane >> 4) << 3);
        Cb[np] = (uint32_t)(row * 128 + ((lane >> 3) & 1) * 16);
        Mb[np] = (uint32_t)((row & 7) << 4);
    }

    float acc[2][8][4];
#pragma unroll
    for (int mi = 0; mi < 2; mi++)
#pragma unroll
        for (int ni = 0; ni < 8; ni++)
#pragma unroll
            for (int q = 0; q < 4; q++) acc[mi][ni][q] = 0.0f;

    const __nv_bfloat16* Ab = g_aext + (size_t)m0 * KEXT;
    const __nv_bfloat16* Bb = g_bext + (size_t)n0 * KEXT;

    gg_load(Ab, Bb, 0, sb, 0, tid);

    int buf = 0;
    for (int c = 0; c < NCHUNK; c++) {
        if (c + 1 < NCHUNK) {
            gg_load(Ab, Bb, c + 1, sb, buf ^ 1, tid);
            CP_WAIT(1);
        } else {
            CP_WAIT(0);
        }
        __syncthreads();

        uint32_t a_sm = sb + buf * SM_BUF;
        uint32_t b_sm = a_sm + 16384;
#pragma unroll
        for (int k16 = 0; k16 < 4; k16++) {
            uint32_t af[2][4], bf[4][4];
#pragma unroll
            for (int mi = 0; mi < 2; mi++)
                ldm_x4(af[mi], a_sm + ((Ca[mi] + k16 * 32) ^ Ma[mi]));
#pragma unroll
            for (int np = 0; np < 4; np++)
                ldm_x4(bf[np], b_sm + ((Cb[np] + k16 * 32) ^ Mb[np]));
#pragma unroll
            for (int mi = 0; mi < 2; mi++)
#pragma unroll
                for (int ni = 0; ni < 8; ni++)
                    mma16816(acc[mi][ni], af[mi],
                             bf[ni >> 1][(ni & 1) * 2],
                             bf[ni >> 1][(ni & 1) * 2 + 1]);
        }
        __syncthreads();
        buf ^= 1;
    }

    // ---- epilogue: bias add + SMEM transpose -> gi[t][n][b] ----
    float* ts = (float*)sm_gg;     // [n_local 128][m_local 132] fp32
    int r = lane >> 2, q = (lane & 3) * 2;
    float bv[8][2];
#pragma unroll
    for (int ni = 0; ni < 8; ni++) {
        bv[ni][0] = bias[n0 + warp_n * 64 + ni * 8 + q];
        bv[ni][1] = bias[n0 + warp_n * 64 + ni * 8 + q + 1];
    }
#pragma unroll
    for (int mi = 0; mi < 2; mi++) {
#pragma unroll
        for (int ni = 0; ni < 8; ni++) {
            int n_l = warp_n * 64 + ni * 8 + q;
            int m_l0 = warp_m * 32 + mi * 16 + r;
            ts[n_l * 132 + m_l0]       = acc[mi][ni][0] + bv[ni][0];
            ts[(n_l + 1) * 132 + m_l0] = acc[mi][ni][1] + bv[ni][1];
            ts[n_l * 132 + m_l0 + 8]       = acc[mi][ni][2] + bv[ni][0];
            ts[(n_l + 1) * 132 + m_l0 + 8] = acc[mi][ni][3] + bv[ni][1];
        }
    }
    __syncthreads();
    int t0 = m0 >> 5;
#pragma unroll
    for (int i = 0; i < 16; i++) {
        int idx4 = tid + i * 256;          // 0..4095 float4 slots
        int t_l = idx4 >> 10;              // 1024 float4 per t region
        int rem = idx4 & 1023;
        int n_l = rem >> 3;
        int b4 = (rem & 7) * 4;
        float4 v = *(const float4*)&ts[n_l * 132 + t_l * 32 + b4];
        *(float4*)&g_gi[((size_t)(t0 + t_l) * G3 + n0 + n_l) * B_SZ + b4] = v;
    }
}

// -------------------- grid barrier (R11 proven version) ---------------------
__device__ __forceinline__ void grid_barrier() {
    __syncthreads();
    if (threadIdx.x == 0) {
        __threadfence();
        unsigned my = atomicAdd(&g_bar, 1u);
        unsigned target = my - (my % NBLK) + NBLK;
        unsigned v;
        do {
            asm volatile("ld.acquire.gpu.b32 %0, [%1];"
                         : "=r"(v) : "l"(&g_bar) : "memory");
            if ((int)(v - target) >= 0) break;
        } while (true);
    }
    __syncthreads();
}

// -------------------- persistent recurrent kernel: tensor-core matvec -------
#define STAGE_OFF 131072                 // 8 warps x 8KB (4 bufs x 2KB)
#define SRED_OFF  196608                 // 8 x 24 x 33 fp32
#define SOUT_OFF  222208                 // 32 x 9 fp32
#define RSM_TOTAL 223488

extern __shared__ unsigned char rsm[];
__global__ void __launch_bounds__(RTHREADS, 1)
rnn_kernel(const float* __restrict__ paddings, const float* __restrict__ b_hh,
           float* __restrict__ out, int out_size) {
    float* sred = (float*)(rsm + SRED_OFF);   // [8 warps][24 n][33] fp32
    float* sout = (float*)(rsm + SOUT_OFF);   // [32][9]
    uint32_t sWb = smem_u32(rsm);             // Wh at +0, Wl at +65536 (bytes)

    int tid = threadIdx.x, wid = tid >> 5, lane = tid & 31;
    int bx = blockIdx.x;
    int ci = wid, b = lane;
    int c = bx * 8 + ci;

    // load pre-swizzled weights (128KB) once
    {
        const float4* src = (const float4*)(g_wt2 + (size_t)bx * 65536);
        float4* dst = (float4*)rsm;
#pragma unroll
        for (int i = 0; i < 32; i++) dst[i * RTHREADS + tid] = src[i * RTHREADS + tid];
    }
    float bh_r = b_hh[c], bh_z = b_hh[H_SZ + c], bh_n = b_hh[2 * H_SZ + c];
    float hreg = 0.0f;
    __syncthreads();

    int ll = lane & 15;
    int half = ll >> 3;
    uint32_t wl_add = (lane >= 16) ? 65536u : 0u;
    uint32_t stg = smem_u32(rsm) + STAGE_OFF + wid * 8192;
    uint32_t a_lane_off = (uint32_t)((lane & 15) * 32 + (lane >> 4) * 16);
    uint32_t lo16 = (uint32_t)(lane * 16);

    const bool has_tail =
        (size_t)out_size >= (size_t)T_STEPS * B_SZ * H_SZ + 2u * B_SZ * H_SZ;

    for (int t = 0; t < T_STEPS; t++) {
        const char* hhg = (const char*)g_hslab[t & 1] + wid * 8192;
        const char* hlg = hhg + 65536;
        // gi loads: [t][n][b] layout -> lane-contiguous (1 wavefront each)
        size_t gbase = ((size_t)t * G3 + c) * B_SZ + b;
        float ir  = __ldg(&g_gi[gbase]);
        float iz  = __ldg(&g_gi[gbase + (size_t)H_SZ * B_SZ]);
        float in_ = __ldg(&g_gi[gbase + (size_t)2 * H_SZ * B_SZ]);
        float p   = __ldg(&paddings[t * B_SZ + b]);

        float acc1[2][3][4], acc2[2][3][4];
#pragma unroll
        for (int mt = 0; mt < 2; mt++)
#pragma unroll
            for (int nt = 0; nt < 3; nt++)
#pragma unroll
                for (int q = 0; q < 4; q++) { acc1[mt][nt][q] = 0.f; acc2[mt][nt][q] = 0.f; }

        // prologue: stage chunks 0..3 (4 commit groups in flight)
#pragma unroll
        for (int j = 0; j < 4; j++) {
            uint32_t dst = stg + j * 2048;
            const char* s0 = hhg + j * 1024;
            const char* s1 = hlg + j * 1024;
            cp16(dst + lo16, s0 + lo16);
            cp16(dst + 512 + lo16, s0 + 512 + lo16);
            cp16(dst + 1024 + lo16, s1 + lo16);
            cp16(dst + 1536 + lo16, s1 + 512 + lo16);
            CP_COMMIT();
        }

#pragma unroll
        for (int k16 = 0; k16 < 8; k16++) {
            if (k16 == 5)      { CP_WAIT(2); }
            else if (k16 == 6) { CP_WAIT(1); }
            else if (k16 == 7) { CP_WAIT(0); }
            else               { CP_WAIT(3); }

            // A fragments from staged smem
            uint32_t abase = stg + (k16 & 3) * 2048;
            uint32_t ah[2][4], al[2][4];
#pragma unroll
            for (int mt = 0; mt < 2; mt++) {
                uint32_t ad = abase + mt * 512 + a_lane_off;
                ldm_x4(ah[mt], ad);
                ldm_x4(al[mt], ad + 1024);
            }
            // refill this buffer with chunk k16+4 (program order after LDSM)
            if (k16 < 4) {
                uint32_t dst = abase;
                const char* s0 = hhg + (k16 + 4) * 1024;
                const char* s1 = hlg + (k16 + 4) * 1024;
                cp16(dst + lo16, s0 + lo16);
                cp16(dst + 512 + lo16, s0 + 512 + lo16);
                cp16(dst + 1024 + lo16, s1 + lo16);
                cp16(dst + 1536 + lo16, s1 + 512 + lo16);
                CP_COMMIT();
            }

            // weights: fused x4 — lanes 0-15 Wh rows, lanes 16-31 Wl rows
            int k16g = wid * 8 + k16;
            uint32_t W4[3][4];
#pragma unroll
            for (int nt = 0; nt < 3; nt++) {
                int n = nt * 8 + (ll & 7);
                uint32_t off = (uint32_t)(k16g * 1024 + n * 32 +
                               ((half ^ ((n >> 2) & 1)) << 4)) + wl_add;
                ldm_x4(W4[nt], sWb + off);
            }
#pragma unroll
            for (int mt = 0; mt < 2; mt++)
#pragma unroll
                for (int nt = 0; nt < 3; nt++) {
                    mma16816(acc1[mt][nt], ah[mt], W4[nt][0], W4[nt][1]);
                    mma16816(acc2[mt][nt], ah[mt], W4[nt][2], W4[nt][3]);
                    mma16816(acc1[mt][nt], al[mt], W4[nt][0], W4[nt][1]);
                }
        }

        // store partials: sred[(wid*24 + n)*33 + m]
#pragma unroll
        for (int mt = 0; mt < 2; mt++)
#pragma unroll
            for (int nt = 0; nt < 3; nt++)
#pragma unroll
                for (int q = 0; q < 4; q++) {
                    int m = mt * 16 + (lane >> 2) + ((q >> 1) << 3);
                    int n = nt * 8 + (lane & 3) * 2 + (q & 1);
                    sred[(wid * 24 + n) * 33 + m] = acc1[mt][nt][q] + acc2[mt][nt][q];
                }
        __syncthreads();

        // reduce 8 warps + gate math: thread = (ci, b)
        float ga = bh_r, gz = bh_z, gn = bh_n;
#pragma unroll
        for (int w = 0; w < 8; w++) {
            const float* bw = sred + w * 24 * 33;
            ga += bw[(0 + ci) * 33 + b];
            gz += bw[(8 + ci) * 33 + b];
            gn += bw[(16 + ci) * 33 + b];
        }
        float rg = 1.0f / (1.0f + __expf(-(ir + ga)));
        float zg = 1.0f / (1.0f + __expf(-(iz + gz)));
        float nn = tanhf(in_ + rg * gn);
        float hn = (1.0f - zg) * nn + zg * hreg;
        hn = p * hreg + (1.0f - p) * hn;
        hreg = hn;
        sout[b * 9 + ci] = hn;
        __syncthreads();

        // writers: out + split-bf16 publish of h into slab layout
        {
            int b2 = tid >> 3, cl = tid & 7;
            float v = sout[b2 * 9 + cl];
            int cg = bx * 8 + cl;
            out[(size_t)t * B_SZ * H_SZ + b2 * H_SZ + cg] = v;
            __nv_bfloat16 hh = __float2bfloat16(v);
            __nv_bfloat16 hl = __float2bfloat16(v - __bfloat162float(hh));
            int w = cg >> 7, k16i = (cg >> 4) & 7, kk = cg & 15;
            int hidx = ((w * 8 + k16i) * 32 + b2) * 16 + kk;
            __nv_bfloat16* hnx = g_hslab[(t + 1) & 1];
            hnx[hidx] = hh;
            hnx[32768 + hidx] = hl;
            if (t == T_STEPS - 1 && has_tail) {
                size_t tail = (size_t)T_STEPS * B_SZ * H_SZ;
                out[tail + b2 * H_SZ + cg] = v;
                out[tail + (size_t)B_SZ * H_SZ + b2 * H_SZ + cg] = v;
            }
        }
        if (t != T_STEPS - 1) grid_barrier();
    }
}

// -------------------- launch --------------------
extern "C" void kernel_launch(void* const* d_in, const int* in_sizes, int n_in,
                              void* d_out, int out_size) {
    const float* X        = (const float*)d_in[0];
    const float* paddings = (const float*)d_in[1];
    const float* W_ih     = (const float*)d_in[2];
    const float* W_hh     = (const float*)d_in[3];
    const float* b_ih     = (const float*)d_in[4];
    const float* b_hh     = (const float*)d_in[5];
    float* out = (float*)d_out;
    (void)in_sizes; (void)n_in;

    pack_kernel<<<(D_SZ * 4096) / 256, 256>>>(W_hh);

    convA_kernel<<<(T_STEPS * B_SZ * D_SZ / 4) / 256, 256>>>(X);
    convB_kernel<<<dim3(G3 / 32, D_SZ / 32), dim3(32, 8)>>>(W_ih);

    cudaFuncSetAttribute(mmagemm_kernel,
                         cudaFuncAttributeMaxDynamicSharedMemorySize, SM_TOTAL_G);
    mmagemm_kernel<<<dim3(G3 / 128, (T_STEPS * B_SZ) / 128), 256, SM_TOTAL_G>>>(b_ih);

    cudaFuncSetAttribute(rnn_kernel,
                         cudaFuncAttributeMaxDynamicSharedMemorySize, RSM_TOTAL);
    rnn_kernel<<<NBLK, RTHREADS, RSM_TOTAL>>>(paddings, b_hh, out, out_size);
}

// round 16
// speedup vs baseline: 1.1799x; 1.0076x over previous
#include <cuda_runtime.h>
#include <cuda_bf16.h>
#include <cstdint>

#define T_STEPS 512
#define B_SZ 32
#define D_SZ 1024
#define H_SZ 1024
#define G3 3072
#define KEXT 3072
#define NBLK 128
#define RTHREADS 256
#define NCHUNK (KEXT / 64)

typedef unsigned long long u64;

// -------------------- device scratch --------------------
// gi in TRANSPOSED layout: [t][n(3072)][b(32)]
__device__ float g_gi[(size_t)T_STEPS * G3 * B_SZ];
__device__ __nv_bfloat16 g_aext[(size_t)T_STEPS * B_SZ * KEXT]; // [m][kext]
__device__ __nv_bfloat16 g_bext[(size_t)G3 * KEXT];             // [n][kext]
__device__ __nv_bfloat16 g_wt2[(size_t)NBLK * 65536];  // per-block smem image (Wh|Wl)
// h slab: [buf][hh: [w8][k16 8][m32][kk16] | hl at +32768 elems]
__device__ __nv_bfloat16 g_hslab[2][65536];
__device__ unsigned g_bar;

// -------------------- smem / mma helpers (base-target ISA only) -------------
__device__ __forceinline__ uint32_t smem_u32(const void* p) {
    uint32_t a;
    asm("{ .reg .u64 t; cvta.to.shared.u64 t, %1; cvt.u32.u64 %0, t; }"
        : "=r"(a) : "l"(p));
    return a;
}
#define SW128(off) ((off) ^ (((off) >> 3) & 0x70))

__device__ __forceinline__ void cp16(uint32_t sm, const void* g) {
    asm volatile("cp.async.cg.shared.global [%0], [%1], 16;" :: "r"(sm), "l"(g));
}
#define CP_COMMIT() asm volatile("cp.async.commit_group;" ::: "memory")
#define CP_WAIT(n)  asm volatile("cp.async.wait_group %0;" :: "n"(n) : "memory")

__device__ __forceinline__ void ldm_x4(uint32_t* r, uint32_t addr) {
    asm volatile("ldmatrix.sync.aligned.m8n8.x4.shared.b16 {%0,%1,%2,%3}, [%4];"
                 : "=r"(r[0]), "=r"(r[1]), "=r"(r[2]), "=r"(r[3]) : "r"(addr));
}
__device__ __forceinline__ void mma16816(float* c, const uint32_t* a,
                                         uint32_t b0, uint32_t b1) {
    asm volatile(
        "mma.sync.aligned.m16n8k16.row.col.f32.bf16.bf16.f32 "
        "{%0,%1,%2,%3}, {%4,%5,%6,%7}, {%8,%9}, {%0,%1,%2,%3};"
        : "+f"(c[0]), "+f"(c[1]), "+f"(c[2]), "+f"(c[3])
        : "r"(a[0]), "r"(a[1]), "r"(a[2]), "r"(a[3]), "r"(b0), "r"(b1));
}

// -------------------- pack: W_hh -> per-block swizzled bf16 split -----------
__global__ void pack_kernel(const float* __restrict__ W_hh) {
    int o = blockIdx.x * blockDim.x + threadIdx.x;   // [k 1024][inner 4096]
    int k = o >> 12;
    int inner = o & 4095;
    float w = 0.0f;
    int r, bx;
    if (inner < 3072) {
        int g = inner >> 10, rem = inner & 1023;
        bx = rem >> 3;
        r = g * 8 + (rem & 7);
        w = W_hh[(size_t)k * G3 + inner];
    } else {
        int pi = inner - 3072;
        bx = pi & 127;
        r = 24 + (pi >> 7);
    }
    __nv_bfloat16 hi = __float2bfloat16(w);
    __nv_bfloat16 lo = __float2bfloat16(w - __bfloat162float(hi));
    int idx = (k >> 4) * 512 + r * 16 +
              (((((k >> 3) & 1) ^ ((r >> 2) & 1))) << 3) + (k & 7);
    size_t base = (size_t)bx * 65536;
    g_wt2[base + idx] = hi;
    g_wt2[base + 32768 + idx] = lo;
    if (o < 2 * 65536)
        ((__nv_bfloat16*)g_hslab)[o] = __float2bfloat16(0.0f);
}

// -------------------- convert A: X -> [xh | xl | xh] bf16 -------------------
__global__ void convA_kernel(const float* __restrict__ X) {
    int idx = blockIdx.x * blockDim.x + threadIdx.x;
    float4 v = *(const float4*)(X + (size_t)idx * 4);
    int m  = idx >> 8;
    int k4 = (idx & 255) * 4;
    __nv_bfloat16 h0 = __float2bfloat16(v.x), h1 = __float2bfloat16(v.y);
    __nv_bfloat16 h2 = __float2bfloat16(v.z), h3 = __float2bfloat16(v.w);
    __nv_bfloat16 l0 = __float2bfloat16(v.x - __bfloat162float(h0));
    __nv_bfloat16 l1 = __float2bfloat16(v.y - __bfloat162float(h1));
    __nv_bfloat16 l2 = __float2bfloat16(v.z - __bfloat162float(h2));
    __nv_bfloat16 l3 = __float2bfloat16(v.w - __bfloat162float(h3));
    __nv_bfloat162 hA = {h0, h1}, hB = {h2, h3}, lA = {l0, l1}, lB = {l2, l3};
    uint2 hp = {*(unsigned*)&hA, *(unsigned*)&hB};
    uint2 lp = {*(unsigned*)&lA, *(unsigned*)&lB};
    __nv_bfloat16* base = g_aext + (size_t)m * KEXT + k4;
    *(uint2*)base = hp;
    *(uint2*)(base + D_SZ) = lp;
    *(uint2*)(base + 2 * D_SZ) = hp;
}

// -------------------- convert B: W_ih^T -> [wh ; wh ; wl] [n][k] bf16 -------
__global__ void convB_kernel(const float* __restrict__ W) {
    __shared__ float tile[32][33];
    int n0 = blockIdx.x * 32, k0 = blockIdx.y * 32;
    int tx = threadIdx.x, ty = threadIdx.y;
#pragma unroll
    for (int j = 0; j < 4; j++) {
        int r = ty * 4 + j;
        tile[r][tx] = W[(size_t)(k0 + r) * G3 + n0 + tx];
    }
    __syncthreads();
#pragma unroll
    for (int j = 0; j < 4; j++) {
        int nl = ty * 4 + j;
        float w = tile[tx][nl];
        __nv_bfloat16 hi = __float2bfloat16(w);
        __nv_bfloat16 lo = __float2bfloat16(w - __bfloat162float(hi));
        __nv_bfloat16* row = g_bext + (size_t)(n0 + nl) * KEXT + k0 + tx;
        row[0] = hi;
        row[D_SZ] = hi;
        row[2 * D_SZ] = lo;
    }
}

// -------------------- mma.sync GEMM: gi = A_ext @ B_ext^T + bias ------------
// 3-stage cp.async pipeline: one __syncthreads per K-chunk.
// Epilogue transposes through SMEM and writes gi in [t][n][b] layout.
#define SM_BUF 32768
#define SM_TOTAL_G 98304            // 3 x 32KB bufs (ts transpose reuses them)

__device__ __forceinline__ void gg_load(const __nv_bfloat16* Ab,
                                        const __nv_bfloat16* Bb,
                                        int c, uint32_t sb, int buf, int tid) {
    size_t koff = (size_t)c * 64;
    uint32_t base = sb + buf * SM_BUF;
#pragma unroll
    for (int i = 0; i < 4; i++) {
        int idx = tid + i * 256;
        int row = idx >> 3, f4 = idx & 7;
        uint32_t sw = SW128((uint32_t)(row * 128 + f4 * 16));
        cp16(base + sw, Ab + (size_t)row * KEXT + koff + f4 * 8);
        cp16(base + 16384 + sw, Bb + (size_t)row * KEXT + koff + f4 * 8);
    }
    CP_COMMIT();
}

extern __shared__ unsigned char sm_gg[];
__global__ void __launch_bounds__(256, 2)
mmagemm_kernel(const float* __restrict__ bias) {
    uint32_t sb = smem_u32(sm_gg);
    int tid = threadIdx.x, wid = tid >> 5, lane = tid & 31;
    int n0 = blockIdx.x * 128, m0 = blockIdx.y * 128;
    int warp_m = wid & 3, warp_n = wid >> 2;

    uint32_t Ca[2], Ma[2];
#pragma unroll
    for (int mi = 0; mi < 2; mi++) {
        int row = warp_m * 32 + mi * 16 + (lane & 15);
        Ca[mi] = (uint32_t)(row * 128 + (lane >> 4) * 16);
        Ma[mi] = (uint32_t)((row & 7) << 4);
    }
    uint32_t Cb[4], Mb[4];
#pragma unroll
    for (int np = 0; np < 4; np++) {
        int row = warp_n * 64 + np * 16 + (lane & 7) + ((lane >> 4) << 3);
        Cb[np] = (uint32_t)(row * 128 + ((lane >> 3) & 1) * 16);
        Mb[np] = (uint32_t)((row & 7) << 4);
    }

    float acc[2][8][4];
#pragma unroll
    for (int mi = 0; mi < 2; mi++)
#pragma unroll
        for (int ni = 0; ni < 8; ni++)
#pragma unroll
            for (int q = 0; q < 4; q++) acc[mi][ni][q] = 0.0f;

    const __nv_bfloat16* Ab = g_aext + (size_t)m0 * KEXT;
    const __nv_bfloat16* Bb = g_bext + (size_t)n0 * KEXT;

    // prologue: 2 chunks in flight
    gg_load(Ab, Bb, 0, sb, 0, tid);
    gg_load(Ab, Bb, 1, sb, 1, tid);

    for (int c = 0; c < NCHUNK; c++) {
        if (c + 1 < NCHUNK) { CP_WAIT(1); } else { CP_WAIT(0); }
        __syncthreads();                // chunk c ready; all prior reads done
        if (c + 2 < NCHUNK)
            gg_load(Ab, Bb, c + 2, sb, (c + 2) % 3, tid);

        uint32_t a_sm = sb + (c % 3) * SM_BUF;
        uint32_t b_sm = a_sm + 16384;
#pragma unroll
        for (int k16 = 0; k16 < 4; k16++) {
            uint32_t af[2][4], bf[4][4];
#pragma unroll
            for (int mi = 0; mi < 2; mi++)
                ldm_x4(af[mi], a_sm + ((Ca[mi] + k16 * 32) ^ Ma[mi]));
#pragma unroll
            for (int np = 0; np < 4; np++)
                ldm_x4(bf[np], b_sm + ((Cb[np] + k16 * 32) ^ Mb[np]));
#pragma unroll
            for (int mi = 0; mi < 2; mi++)
#pragma unroll
                for (int ni = 0; ni < 8; ni++)
                    mma16816(acc[mi][ni], af[mi],
                             bf[ni >> 1][(ni & 1) * 2],
                             bf[ni >> 1][(ni & 1) * 2 + 1]);
        }
    }
    __syncthreads();                    // all reads done before ts overwrite

    // ---- epilogue: bias add + SMEM transpose -> gi[t][n][b] ----
    float* ts = (float*)sm_gg;     // [n_local 128][m_local 132] fp32
    int r = lane >> 2, q = (lane & 3) * 2;
    float bv[8][2];
#pragma unroll
    for (int ni = 0; ni < 8; ni++) {
        bv[ni][0] = bias[n0 + warp_n * 64 + ni * 8 + q];
        bv[ni][1] = bias[n0 + warp_n * 64 + ni * 8 + q + 1];
    }
#pragma unroll
    for (int mi = 0; mi < 2; mi++) {
#pragma unroll
        for (int ni = 0; ni < 8; ni++) {
            int n_l = warp_n * 64 + ni * 8 + q;
            int m_l0 = warp_m * 32 + mi * 16 + r;
            ts[n_l * 132 + m_l0]       = acc[mi][ni][0] + bv[ni][0];
            ts[(n_l + 1) * 132 + m_l0] = acc[mi][ni][1] + bv[ni][1];
            ts[n_l * 132 + m_l0 + 8]       = acc[mi][ni][2] + bv[ni][0];
            ts[(n_l + 1) * 132 + m_l0 + 8] = acc[mi][ni][3] + bv[ni][1];
        }
    }
    __syncthreads();
    int t0 = m0 >> 5;
#pragma unroll
    for (int i = 0; i < 16; i++) {
        int idx4 = tid + i * 256;          // 0..4095 float4 slots
        int t_l = idx4 >> 10;              // 1024 float4 per t region
        int rem = idx4 & 1023;
        int n_l = rem >> 3;
        int b4 = (rem & 7) * 4;
        float4 v = *(const float4*)&ts[n_l * 132 + t_l * 32 + b4];
        *(float4*)&g_gi[((size_t)(t0 + t_l) * G3 + n0 + n_l) * B_SZ + b4] = v;
    }
}

// -------------------- grid barrier (R11 proven version) ---------------------
__device__ __forceinline__ void grid_barrier() {
    __syncthreads();
    if (threadIdx.x == 0) {
        __threadfence();
        unsigned my = atomicAdd(&g_bar, 1u);
        unsigned target = my - (my % NBLK) + NBLK;
        unsigned v;
        do {
            asm volatile("ld.acquire.gpu.b32 %0, [%1];"
                         : "=r"(v) : "l"(&g_bar) : "memory");
            if ((int)(v - target) >= 0) break;
        } while (true);
    }
    __syncthreads();
}

// -------------------- persistent recurrent kernel: tensor-core matvec -------
#define STAGE_OFF 131072                 // 8 warps x 8KB (4 bufs x 2KB)
#define SRED_OFF  196608                 // 8 x 24 x 33 fp32
#define SOUT_OFF  222208                 // 32 x 9 fp32
#define RSM_TOTAL 223488

extern __shared__ unsigned char rsm[];
__global__ void __launch_bounds__(RTHREADS, 1)
rnn_kernel(const float* __restrict__ paddings, const float* __restrict__ b_hh,
           float* __restrict__ out, int out_size) {
    float* sred = (float*)(rsm + SRED_OFF);   // [8 warps][24 n][33] fp32
    float* sout = (float*)(rsm + SOUT_OFF);   // [32][9]
    uint32_t sWb = smem_u32(rsm);             // Wh at +0, Wl at +65536 (bytes)

    int tid = threadIdx.x, wid = tid >> 5, lane = tid & 31;
    int bx = blockIdx.x;
    int ci = wid, b = lane;
    int c = bx * 8 + ci;

    // load pre-swizzled weights (128KB) once
    {
        const float4* src = (const float4*)(g_wt2 + (size_t)bx * 65536);
        float4* dst = (float4*)rsm;
#pragma unroll
        for (int i = 0; i < 32; i++) dst[i * RTHREADS + tid] = src[i * RTHREADS + tid];
    }
    float bh_r = b_hh[c], bh_z = b_hh[H_SZ + c], bh_n = b_hh[2 * H_SZ + c];
    float hreg = 0.0f;
    __syncthreads();

    int ll = lane & 15;
    int half = ll >> 3;
    uint32_t wl_add = (lane >= 16) ? 65536u : 0u;
    uint32_t stg = smem_u32(rsm) + STAGE_OFF + wid * 8192;
    uint32_t a_lane_off = (uint32_t)((lane & 15) * 32 + (lane >> 4) * 16);
    uint32_t lo16 = (uint32_t)(lane * 16);

    const bool has_tail =
        (size_t)out_size >= (size_t)T_STEPS * B_SZ * H_SZ + 2u * B_SZ * H_SZ;

    for (int t = 0; t < T_STEPS; t++) {
        const char* hhg = (const char*)g_hslab[t & 1] + wid * 8192;
        const char* hlg = hhg + 65536;
        // gi loads: [t][n][b] layout -> lane-contiguous (1 wavefront each)
        size_t gbase = ((size_t)t * G3 + c) * B_SZ + b;
        float ir  = __ldg(&g_gi[gbase]);
        float iz  = __ldg(&g_gi[gbase + (size_t)H_SZ * B_SZ]);
        float in_ = __ldg(&g_gi[gbase + (size_t)2 * H_SZ * B_SZ]);
        float p   = __ldg(&paddings[t * B_SZ + b]);

        float acc1[2][3][4], acc2[2][3][4];
#pragma unroll
        for (int mt = 0; mt < 2; mt++)
#pragma unroll
            for (int nt = 0; nt < 3; nt++)
#pragma unroll
                for (int q = 0; q < 4; q++) { acc1[mt][nt][q] = 0.f; acc2[mt][nt][q] = 0.f; }

        // prologue: stage chunks 0..3 (4 commit groups in flight)
#pragma unroll
        for (int j = 0; j < 4; j++) {
            uint32_t dst = stg + j * 2048;
            const char* s0 = hhg + j * 1024;
            const char* s1 = hlg + j * 1024;
            cp16(dst + lo16, s0 + lo16);
            cp16(dst + 512 + lo16, s0 + 512 + lo16);
            cp16(dst + 1024 + lo16, s1 + lo16);
            cp16(dst + 1536 + lo16, s1 + 512 + lo16);
            CP_COMMIT();
        }

#pragma unroll
        for (int k16 = 0; k16 < 8; k16++) {
            if (k16 == 5)      { CP_WAIT(2); }
            else if (k16 == 6) { CP_WAIT(1); }
            else if (k16 == 7) { CP_WAIT(0); }
            else               { CP_WAIT(3); }

            // A fragments from staged smem
            uint32_t abase = stg + (k16 & 3) * 2048;
            uint32_t ah[2][4], al[2][4];
#pragma unroll
            for (int mt = 0; mt < 2; mt++) {
                uint32_t ad = abase + mt * 512 + a_lane_off;
                ldm_x4(ah[mt], ad);
                ldm_x4(al[mt], ad + 1024);
            }
            // refill this buffer with chunk k16+4 (program order after LDSM)
            if (k16 < 4) {
                uint32_t dst = abase;
                const char* s0 = hhg + (k16 + 4) * 1024;
                const char* s1 = hlg + (k16 + 4) * 1024;
                cp16(dst + lo16, s0 + lo16);
                cp16(dst + 512 + lo16, s0 + 512 + lo16);
                cp16(dst + 1024 + lo16, s1 + lo16);
                cp16(dst + 1536 + lo16, s1 + 512 + lo16);
                CP_COMMIT();
            }

            // weights: fused x4 — lanes 0-15 Wh rows, lanes 16-31 Wl rows
            int k16g = wid * 8 + k16;
            uint32_t W4[3][4];
#pragma unroll
            for (int nt = 0; nt < 3; nt++) {
                int n = nt * 8 + (ll & 7);
                uint32_t off = (uint32_t)(k16g * 1024 + n * 32 +
                               ((half ^ ((n >> 2) & 1)) << 4)) + wl_add;
                ldm_x4(W4[nt], sWb + off);
            }
#pragma unroll
            for (int mt = 0; mt < 2; mt++)
#pragma unroll
                for (int nt = 0; nt < 3; nt++) {
                    mma16816(acc1[mt][nt], ah[mt], W4[nt][0], W4[nt][1]);
                    mma16816(acc2[mt][nt], ah[mt], W4[nt][2], W4[nt][3]);
                    mma16816(acc1[mt][nt], al[mt], W4[nt][0], W4[nt][1]);
                }
        }

        // store partials: sred[(wid*24 + n)*33 + m]
#pragma unroll
        for (int mt = 0; mt < 2; mt++)
#pragma unroll
            for (int nt = 0; nt < 3; nt++)
#pragma unroll
                for (int q = 0; q < 4; q++) {
                    int m = mt * 16 + (lane >> 2) + ((q >> 1) << 3);
                    int n = nt * 8 + (lane & 3) * 2 + (q & 1);
                    sred[(wid * 24 + n) * 33 + m] = acc1[mt][nt][q] + acc2[mt][nt][q];
                }
        __syncthreads();

        // reduce 8 warps + gate math: thread = (ci, b)
        float ga = bh_r, gz = bh_z, gn = bh_n;
#pragma unroll
        for (int w = 0; w < 8; w++) {
            const float* bw = sred + w * 24 * 33;
            ga += bw[(0 + ci) * 33 + b];
            gz += bw[(8 + ci) * 33 + b];
            gn += bw[(16 + ci) * 33 + b];
        }
        float rg = 1.0f / (1.0f + __expf(-(ir + ga)));
        float zg = 1.0f / (1.0f + __expf(-(iz + gz)));
        float nn = tanhf(in_ + rg * gn);
        float hn = (1.0f - zg) * nn + zg * hreg;
        hn = p * hreg + (1.0f - p) * hn;
        hreg = hn;
        sout[b * 9 + ci] = hn;
        __syncthreads();

        // writers: out + split-bf16 publish of h into slab layout
        {
            int b2 = tid >> 3, cl = tid & 7;
            float v = sout[b2 * 9 + cl];
            int cg = bx * 8 + cl;
            out[(size_t)t * B_SZ * H_SZ + b2 * H_SZ + cg] = v;
            __nv_bfloat16 hh = __float2bfloat16(v);
            __nv_bfloat16 hl = __float2bfloat16(v - __bfloat162float(hh));
            int w = cg >> 7, k16i = (cg >> 4) & 7, kk = cg & 15;
            int hidx = ((w * 8 + k16i) * 32 + b2) * 16 + kk;
            __nv_bfloat16* hnx = g_hslab[(t + 1) & 1];
            hnx[hidx] = hh;
            hnx[32768 + hidx] = hl;
            if (t == T_STEPS - 1 && has_tail) {
                size_t tail = (size_t)T_STEPS * B_SZ * H_SZ;
                out[tail + b2 * H_SZ + cg] = v;
                out[tail + (size_t)B_SZ * H_SZ + b2 * H_SZ + cg] = v;
            }
        }
        if (t != T_STEPS - 1) grid_barrier();
    }
}

// -------------------- launch --------------------
extern "C" void kernel_launch(void* const* d_in, const int* in_sizes, int n_in,
                              void* d_out, int out_size) {
    const float* X        = (const float*)d_in[0];
    const float* paddings = (const float*)d_in[1];
    const float* W_ih     = (const float*)d_in[2];
    const float* W_hh     = (const float*)d_in[3];
    const float* b_ih     = (const float*)d_in[4];
    const float* b_hh     = (const float*)d_in[5];
    float* out = (float*)d_out;
    (void)in_sizes; (void)n_in;

    pack_kernel<<<(D_SZ * 4096) / 256, 256>>>(W_hh);

    convA_kernel<<<(T_STEPS * B_SZ * D_SZ / 4) / 256, 256>>>(X);
    convB_kernel<<<dim3(G3 / 32, D_SZ / 32), dim3(32, 8)>>>(W_ih);

    cudaFuncSetAttribute(mmagemm_kernel,
                         cudaFuncAttributeMaxDynamicSharedMemorySize, SM_TOTAL_G);
    mmagemm_kernel<<<dim3(G3 / 128, (T_STEPS * B_SZ) / 128), 256, SM_TOTAL_G>>>(b_ih);

    cudaFuncSetAttribute(rnn_kernel,
                         cudaFuncAttributeMaxDynamicSharedMemorySize, RSM_TOTAL);
    rnn_kernel<<<NBLK, RTHREADS, RSM_TOTAL>>>(paddings, b_hh, out, out_size);
}